// round 1
// baseline (speedup 1.0000x reference)
#include <cuda_runtime.h>
#include <cuda_bf16.h>
#include <float.h>

// Problem shape (fixed by setup_inputs): B=32, C=512, H=W=64
#define B_DIM 32
#define C_DIM 512
#define HW 4096
#define BC (B_DIM * C_DIM)        // 16384 planes
#define ROWBLKS 16                // row-blocks per batch in softmax kernel
#define ROWS_PER_BLK (C_DIM / ROWBLKS)  // 32

// Device scratch (no allocations allowed)
__device__ float g_d[BC];
__device__ float g_e[BC];
__device__ float g_pm[ROWBLKS * BC];   // partial f_max sums, deterministic layout
__device__ float g_pe[ROWBLKS * BC];   // partial f_mean sums

// ---------------------------------------------------------------------------
// Kernel 1: per-(b,c) plane pooling. max + mean over 4096 elements.
// One block per plane, 256 threads, 4x float4 per thread.
// ---------------------------------------------------------------------------
__global__ __launch_bounds__(256) void pool_kernel(const float* __restrict__ x) {
    const int plane = blockIdx.x;                 // b*C + c
    const float4* __restrict__ p =
        reinterpret_cast<const float4*>(x + (size_t)plane * HW);
    const int t = threadIdx.x;

    float mx = -FLT_MAX;
    float sm = 0.0f;
#pragma unroll
    for (int i = 0; i < 4; i++) {
        float4 v = p[t + i * 256];
        mx = fmaxf(mx, fmaxf(fmaxf(v.x, v.y), fmaxf(v.z, v.w)));
        sm += (v.x + v.y) + (v.z + v.w);
    }
    // warp reduce
#pragma unroll
    for (int o = 16; o; o >>= 1) {
        mx = fmaxf(mx, __shfl_xor_sync(0xFFFFFFFFu, mx, o));
        sm += __shfl_xor_sync(0xFFFFFFFFu, sm, o);
    }
    __shared__ float smx[8], ssm[8];
    const int w = t >> 5;
    if ((t & 31) == 0) { smx[w] = mx; ssm[w] = sm; }
    __syncthreads();
    if (t == 0) {
        mx = smx[0]; sm = ssm[0];
#pragma unroll
        for (int i = 1; i < 8; i++) { mx = fmaxf(mx, smx[i]); sm += ssm[i]; }
        g_d[plane] = mx;
        g_e[plane] = sm * (1.0f / (float)HW);
    }
}

// ---------------------------------------------------------------------------
// Kernel 2: for each batch b, rows i in [rb*32, rb*32+32):
//   v_j = d_i*d_j + e_i*e_j ; softmax over j ; accumulate
//   fmax_j += d_i * p_ij ; fmean_j += e_i * p_ij
// Grid (ROWBLKS, B), 512 threads (thread = column j).
// Deterministic: partials written per (rb) slot, no atomics.
// ---------------------------------------------------------------------------
__global__ __launch_bounds__(512) void mix_kernel() {
    const int b  = blockIdx.y;
    const int rb = blockIdx.x;
    const int j  = threadIdx.x;

    __shared__ float ds[C_DIM], es[C_DIM];
    __shared__ float red[16];
    __shared__ float bc;

    ds[j] = g_d[b * C_DIM + j];
    es[j] = g_e[b * C_DIM + j];
    __syncthreads();

    const float dj = ds[j];
    const float ej = es[j];
    float accM = 0.0f, accE = 0.0f;

    for (int r = 0; r < ROWS_PER_BLK; r++) {
        const int i = rb * ROWS_PER_BLK + r;
        const float di = ds[i];
        const float ei = es[i];
        const float v = di * dj + ei * ej;

        // block max over 512 threads
        float m = v;
#pragma unroll
        for (int o = 16; o; o >>= 1) m = fmaxf(m, __shfl_xor_sync(0xFFFFFFFFu, m, o));
        if ((j & 31) == 0) red[j >> 5] = m;
        __syncthreads();
        if (j < 16) {
            m = red[j];
#pragma unroll
            for (int o = 8; o; o >>= 1) m = fmaxf(m, __shfl_xor_sync(0xFFFFu, m, o));
            if (j == 0) bc = m;
        }
        __syncthreads();
        m = bc;

        const float w = __expf(v - m);

        // block sum
        float s = w;
#pragma unroll
        for (int o = 16; o; o >>= 1) s += __shfl_xor_sync(0xFFFFFFFFu, s, o);
        if ((j & 31) == 0) red[j >> 5] = s;
        __syncthreads();
        if (j < 16) {
            s = red[j];
#pragma unroll
            for (int o = 8; o; o >>= 1) s += __shfl_xor_sync(0xFFFFu, s, o);
            if (j == 0) bc = s;
        }
        __syncthreads();
        const float inv = 1.0f / bc;
        accM += di * w * inv;
        accE += ei * w * inv;
        __syncthreads();   // protect red/bc reuse next iteration
    }

    g_pm[rb * BC + b * C_DIM + j] = accM;
    g_pe[rb * BC + b * C_DIM + j] = accE;
}

// ---------------------------------------------------------------------------
// Kernel 3: finalize f[b,c] = alpha*fmax + beta*fmean, broadcast over HW.
// One block per plane, 256 threads, 4x float4 stores.
// ---------------------------------------------------------------------------
__global__ __launch_bounds__(256) void bcast_kernel(const float* __restrict__ alpha,
                                                    const float* __restrict__ beta,
                                                    float* __restrict__ out) {
    const int plane = blockIdx.x;
    __shared__ float fval;
    if (threadIdx.x == 0) {
        float fm = 0.0f, fe = 0.0f;
#pragma unroll
        for (int r = 0; r < ROWBLKS; r++) {
            fm += g_pm[r * BC + plane];
            fe += g_pe[r * BC + plane];
        }
        fval = alpha[0] * fm + beta[0] * fe;
    }
    __syncthreads();
    const float v = fval;
    const float4 v4 = make_float4(v, v, v, v);
    float4* __restrict__ o = reinterpret_cast<float4*>(out + (size_t)plane * HW);
    const int t = threadIdx.x;
#pragma unroll
    for (int i = 0; i < 4; i++) o[t + i * 256] = v4;
}

// ---------------------------------------------------------------------------
extern "C" void kernel_launch(void* const* d_in, const int* in_sizes, int n_in,
                              void* d_out, int out_size) {
    const float* x     = (const float*)d_in[0];
    const float* alpha = (const float*)d_in[1];
    const float* beta  = (const float*)d_in[2];
    float* out = (float*)d_out;

    pool_kernel<<<BC, 256>>>(x);
    mix_kernel<<<dim3(ROWBLKS, B_DIM), C_DIM>>>();
    bcast_kernel<<<BC, 256>>>(alpha, beta, out);
}

// round 3
// speedup vs baseline: 1.2557x; 1.2557x over previous
#include <cuda_runtime.h>
#include <cuda_bf16.h>
#include <float.h>

// Problem shape (fixed by setup_inputs): B=32, C=512, H=W=64
#define B_DIM 32
#define C_DIM 512
#define HW 4096
#define BC (B_DIM * C_DIM)        // 16384 planes

// Device scratch (no allocations allowed)
__device__ float g_d[BC];
__device__ float g_e[BC];
__device__ float g_c[BC];   // per-row folded softmax constant: exp(-m_i)/s_i
__device__ float g_f[BC];   // final per-plane value

// ---------------------------------------------------------------------------
// Kernel 1: per-(b,c) plane pooling. max + mean over 4096 elements.
// One block per plane, 256 threads, 4x float4 per thread. DRAM-bound (~41us).
// ---------------------------------------------------------------------------
__global__ __launch_bounds__(256) void pool_kernel(const float* __restrict__ x) {
    const int plane = blockIdx.x;                 // b*C + c
    const float4* __restrict__ p =
        reinterpret_cast<const float4*>(x + (size_t)plane * HW);
    const int t = threadIdx.x;

    float mx = -FLT_MAX;
    float sm = 0.0f;
#pragma unroll
    for (int i = 0; i < 4; i++) {
        float4 v = p[t + i * 256];
        mx = fmaxf(mx, fmaxf(fmaxf(v.x, v.y), fmaxf(v.z, v.w)));
        sm += (v.x + v.y) + (v.z + v.w);
    }
#pragma unroll
    for (int o = 16; o; o >>= 1) {
        mx = fmaxf(mx, __shfl_xor_sync(0xFFFFFFFFu, mx, o));
        sm += __shfl_xor_sync(0xFFFFFFFFu, sm, o);
    }
    __shared__ float smx[8], ssm[8];
    const int w = t >> 5;
    if ((t & 31) == 0) { smx[w] = mx; ssm[w] = sm; }
    __syncthreads();
    if (t == 0) {
        mx = smx[0]; sm = ssm[0];
#pragma unroll
        for (int i = 1; i < 8; i++) { mx = fmaxf(mx, smx[i]); sm += ssm[i]; }
        g_d[plane] = mx;
        g_e[plane] = sm * (1.0f / (float)HW);
    }
}

// ---------------------------------------------------------------------------
// Kernel 2: warp-per-row softmax stats. Row (b,i): v_ij = d_i*d_j + e_i*e_j.
// Compute m_i = max_j v, s_i = sum_j exp(v - m), store c_i = exp(-m_i)/s_i.
// Warp shuffles only — zero block barriers.
// Grid: 2048 blocks x 256 threads (8 warps/block, warp = one row).
// ---------------------------------------------------------------------------
__global__ __launch_bounds__(256) void rowstats_kernel() {
    const int warp_g = (blockIdx.x * 256 + threadIdx.x) >> 5;   // 0..16383
    const int lane   = threadIdx.x & 31;
    const int b      = warp_g >> 9;          // /512
    const int i      = warp_g & 511;
    const int base   = b * C_DIM;

    const float di = g_d[base + i];
    const float ei = g_e[base + i];

    float vj[16];
    float m = -FLT_MAX;
#pragma unroll
    for (int k = 0; k < 16; k++) {
        const int j = lane + k * 32;
        const float v = di * g_d[base + j] + ei * g_e[base + j];
        vj[k] = v;
        m = fmaxf(m, v);
    }
#pragma unroll
    for (int o = 16; o; o >>= 1) m = fmaxf(m, __shfl_xor_sync(0xFFFFFFFFu, m, o));

    float s = 0.0f;
#pragma unroll
    for (int k = 0; k < 16; k++) s += __expf(vj[k] - m);
#pragma unroll
    for (int o = 16; o; o >>= 1) s += __shfl_xor_sync(0xFFFFFFFFu, s, o);

    if (lane == 0) g_c[base + i] = __expf(-m) / s;
}

// ---------------------------------------------------------------------------
// Kernel 3: thread-per-column accumulation, zero reductions.
//   f_j = alpha * sum_i d_i * exp(v_ij) * c_i + beta * sum_i e_i * exp(v_ij) * c_i
// Grid (4, 32) x 128 threads. d/e/c staged in SMEM per batch. One sync total.
// ---------------------------------------------------------------------------
__global__ __launch_bounds__(128) void accum_kernel(const float* __restrict__ alpha,
                                                    const float* __restrict__ beta) {
    const int b    = blockIdx.y;
    const int j    = blockIdx.x * 128 + threadIdx.x;
    const int base = b * C_DIM;

    __shared__ float ds[C_DIM], es[C_DIM], cs[C_DIM];
#pragma unroll
    for (int k = 0; k < 4; k++) {
        const int idx = threadIdx.x + k * 128;
        ds[idx] = g_d[base + idx];
        es[idx] = g_e[base + idx];
        cs[idx] = g_c[base + idx];
    }
    __syncthreads();

    const float dj = ds[j & 511];
    const float ej = es[j & 511];
    float accM = 0.0f, accE = 0.0f;
#pragma unroll 8
    for (int i = 0; i < C_DIM; i++) {
        const float di = ds[i];
        const float ei = es[i];
        const float w  = __expf(di * dj + ei * ej) * cs[i];
        accM = fmaf(di, w, accM);
        accE = fmaf(ei, w, accE);
    }
    g_f[base + j] = alpha[0] * accM + beta[0] * accE;
}

// ---------------------------------------------------------------------------
// Kernel 4: broadcast f[b,c] over the HW plane. DRAM-write-bound (~38us).
// ---------------------------------------------------------------------------
__global__ __launch_bounds__(256) void bcast_kernel(float* __restrict__ out) {
    const int plane = blockIdx.x;
    const float v = g_f[plane];
    const float4 v4 = make_float4(v, v, v, v);
    float4* __restrict__ o = reinterpret_cast<float4*>(out + (size_t)plane * HW);
    const int t = threadIdx.x;
#pragma unroll
    for (int i = 0; i < 4; i++) o[t + i * 256] = v4;
}

// ---------------------------------------------------------------------------
extern "C" void kernel_launch(void* const* d_in, const int* in_sizes, int n_in,
                              void* d_out, int out_size) {
    const float* x     = (const float*)d_in[0];
    const float* alpha = (const float*)d_in[1];
    const float* beta  = (const float*)d_in[2];
    float* out = (float*)d_out;

    pool_kernel<<<BC, 256>>>(x);
    rowstats_kernel<<<BC / 8, 256>>>();
    accum_kernel<<<dim3(4, B_DIM), 128>>>(alpha, beta);
    bcast_kernel<<<BC, 256>>>(out);
}